// round 1
// baseline (speedup 1.0000x reference)
#include <cuda_runtime.h>

#define N_NODES  100000
#define N_EDGES  1600000
#define HIDDEN   64
#define EMB      2
#define N_GRAPHS 64

// -------- scratch (device globals; no allocation allowed) --------
__device__ float  g_dinv[N_NODES];        // deg during pass A, then rsqrt(deg)
__device__ float  g_agg1[N_NODES];        // scalar layer-1 aggregation a_n
__device__ float  g_norm[N_EDGES];        // per-edge norm cached for pass C
__device__ float2 g_hh[N_NODES];          // h2 @ W2  (2 floats per node)
__device__ float2 g_out2[N_NODES];        // layer-2 aggregation output
__device__ double g_sum, g_sumsq;         // for batchnorm mean/var
__device__ float  g_S[HIDDEN], g_T[HIDDEN];
__device__ float  g_pool[N_GRAPHS * 2];
__device__ float  g_cnt[N_GRAPHS];

// K1: init deg=1 (self-loop weight), zero accumulators
__global__ void k_init() {
    int n = blockIdx.x * blockDim.x + threadIdx.x;
    if (n < N_NODES) g_dinv[n] = 1.0f;
    if (n < N_GRAPHS * 2) g_pool[n] = 0.0f;
    if (n < N_GRAPHS)     g_cnt[n] = 0.0f;
    if (n == 0) { g_sum = 0.0; g_sumsq = 0.0; }
}

// K2: deg[d] += w  over all edges
__global__ void k_deg(const int* __restrict__ dst, const float* __restrict__ ew) {
    int e = blockIdx.x * blockDim.x + threadIdx.x;
    if (e < N_EDGES) atomicAdd(&g_dinv[__ldg(&dst[e])], __ldg(&ew[e]));
}

// K3: dinv = rsqrt(deg); seed agg1 with self-loop term x[n]*dinv^2
__global__ void k_dinv(const float* __restrict__ x) {
    int n = blockIdx.x * blockDim.x + threadIdx.x;
    if (n >= N_NODES) return;
    float di = rsqrtf(g_dinv[n]);   // deg >= 1 always (self-loop)
    g_dinv[n] = di;
    g_agg1[n] = __ldg(&x[n]) * di * di;
}

// K4: edge pass B — agg1[d] += x[s]*norm ; cache norm
__global__ void k_agg1(const int* __restrict__ src, const int* __restrict__ dst,
                       const float* __restrict__ ew, const float* __restrict__ x) {
    int e = blockIdx.x * blockDim.x + threadIdx.x;
    if (e >= N_EDGES) return;
    int s = __ldg(&src[e]);
    int d = __ldg(&dst[e]);
    float nv = g_dinv[s] * __ldg(&ew[e]) * g_dinv[d];
    g_norm[e] = nv;
    atomicAdd(&g_agg1[d], __ldg(&x[s]) * nv);
}

// K5: sum & sumsq of agg1 (for batchnorm over the rank-1 layer-1 output)
__global__ void k_reduce() {
    __shared__ float ss[256], sq[256];
    int tid = threadIdx.x;
    float a = 0.f, b = 0.f;
    for (int n = blockIdx.x * blockDim.x + tid; n < N_NODES; n += gridDim.x * blockDim.x) {
        float v = g_agg1[n];
        a += v; b += v * v;
    }
    ss[tid] = a; sq[tid] = b;
    __syncthreads();
    for (int st = 128; st > 0; st >>= 1) {
        if (tid < st) { ss[tid] += ss[tid + st]; sq[tid] += sq[tid + st]; }
        __syncthreads();
    }
    if (tid == 0) {
        atomicAdd(&g_sum,   (double)ss[0]);
        atomicAdd(&g_sumsq, (double)sq[0]);
    }
}

// K6: per-column affine constants S_j, T_j  (bn + gamma/beta folded)
__global__ void k_bnconst(const float* __restrict__ W1, const float* __restrict__ b1,
                          const float* __restrict__ gamma, const float* __restrict__ beta) {
    int j = threadIdx.x;
    if (j >= HIDDEN) return;
    float m   = (float)(g_sum / (double)N_NODES);
    float var = (float)(g_sumsq / (double)N_NODES) - m * m;
    float w = __ldg(&W1[j]);
    // column mean mu_j = m*w + b1_j ; column var = var * w^2
    float inv = rsqrtf(var * w * w + 1e-5f);
    float sj = w * inv * __ldg(&gamma[j]);
    g_S[j] = sj;
    // bn(n,j) = (a_n*w + b1 - mu_j)*inv*gamma + beta = (a_n - m)*sj + beta
    g_T[j] = __ldg(&beta[j]) - m * sj;
}

// K7: hh[n] = relu(a_n*S + T) @ W2 ; seed out2 with self-loop term
__global__ void k_hh(const float* __restrict__ W2) {
    __shared__ float sS[HIDDEN], sT[HIDDEN], sW0[HIDDEN], sW1[HIDDEN];
    int tid = threadIdx.x;
    if (tid < HIDDEN) {
        sS[tid] = g_S[tid];
        sT[tid] = g_T[tid];
        sW0[tid] = __ldg(&W2[tid * EMB + 0]);
        sW1[tid] = __ldg(&W2[tid * EMB + 1]);
    }
    __syncthreads();
    int n = blockIdx.x * blockDim.x + tid;
    if (n >= N_NODES) return;
    float a = g_agg1[n];
    float acc0 = 0.f, acc1 = 0.f;
#pragma unroll
    for (int j = 0; j < HIDDEN; j++) {
        float h = fmaxf(fmaf(a, sS[j], sT[j]), 0.0f);
        acc0 = fmaf(h, sW0[j], acc0);
        acc1 = fmaf(h, sW1[j], acc1);
    }
    float di = g_dinv[n];
    float d2 = di * di;
    g_hh[n]   = make_float2(acc0, acc1);
    g_out2[n] = make_float2(acc0 * d2, acc1 * d2);   // self-loop seed
}

// K8: edge pass C — out2[d] += hh[s] * norm
__global__ void k_agg2(const int* __restrict__ src, const int* __restrict__ dst) {
    int e = blockIdx.x * blockDim.x + threadIdx.x;
    if (e >= N_EDGES) return;
    float nv = g_norm[e];
    int s = __ldg(&src[e]);
    int d = __ldg(&dst[e]);
    float2 h = g_hh[s];
    atomicAdd(&g_out2[d].x, h.x * nv);
    atomicAdd(&g_out2[d].y, h.y * nv);
}

// K9: global mean pool (batch sorted) — smem pre-aggregation then few globals
__global__ void k_pool(const int* __restrict__ batch) {
    __shared__ float p0[N_GRAPHS], p1[N_GRAPHS], pc[N_GRAPHS];
    int tid = threadIdx.x;
    if (tid < N_GRAPHS) { p0[tid] = 0.f; p1[tid] = 0.f; pc[tid] = 0.f; }
    __syncthreads();
    int n = blockIdx.x * blockDim.x + tid;
    if (n < N_NODES) {
        int g = __ldg(&batch[n]);
        float2 v = g_out2[n];
        atomicAdd(&p0[g], v.x);
        atomicAdd(&p1[g], v.y);
        atomicAdd(&pc[g], 1.0f);
    }
    __syncthreads();
    if (tid < N_GRAPHS) {
        if (pc[tid] != 0.f) {
            atomicAdd(&g_pool[tid * 2 + 0], p0[tid]);
            atomicAdd(&g_pool[tid * 2 + 1], p1[tid]);
            atomicAdd(&g_cnt[tid], pc[tid]);
        }
    }
}

// K10: divide + b2, write output [N_GRAPHS, EMB] float32
__global__ void k_final(const float* __restrict__ b2, float* __restrict__ out) {
    int g = threadIdx.x;
    if (g >= N_GRAPHS) return;
    float c = fmaxf(g_cnt[g], 1.0f);
    out[g * 2 + 0] = g_pool[g * 2 + 0] / c + __ldg(&b2[0]);
    out[g * 2 + 1] = g_pool[g * 2 + 1] / c + __ldg(&b2[1]);
}

extern "C" void kernel_launch(void* const* d_in, const int* in_sizes, int n_in,
                              void* d_out, int out_size) {
    const float* x     = (const float*)d_in[0];
    const int*   ei    = (const int*)  d_in[1];   // [2, E]
    const float* ew    = (const float*)d_in[2];
    const int*   batch = (const int*)  d_in[3];
    const float* W1    = (const float*)d_in[4];
    const float* b1    = (const float*)d_in[5];
    const float* gamma = (const float*)d_in[6];
    const float* beta  = (const float*)d_in[7];
    const float* W2    = (const float*)d_in[8];
    const float* b2    = (const float*)d_in[9];
    float* out = (float*)d_out;

    const int* src = ei;
    const int* dst = ei + N_EDGES;

    const int BT = 256;
    const int GN = (N_NODES + BT - 1) / BT;
    const int GE = (N_EDGES + BT - 1) / BT;

    k_init   <<<GN, BT>>>();
    k_deg    <<<GE, BT>>>(dst, ew);
    k_dinv   <<<GN, BT>>>(x);
    k_agg1   <<<GE, BT>>>(src, dst, ew, x);
    k_reduce <<<148, 256>>>();
    k_bnconst<<<1, 64>>>(W1, b1, gamma, beta);
    k_hh     <<<GN, BT>>>(W2);
    k_agg2   <<<GE, BT>>>(src, dst);
    k_pool   <<<GN, BT>>>(batch);
    k_final  <<<1, 64>>>(b2, out);
}

// round 2
// speedup vs baseline: 1.1948x; 1.1948x over previous
#include <cuda_runtime.h>

#define N_NODES  100000
#define N_EDGES  1600000
#define HIDDEN   64
#define EMB      2
#define N_GRAPHS 64

// -------- scratch (device globals) --------
__device__ float  g_dinv[N_NODES];        // deg (pass A) -> rsqrt(deg+1)
__device__ float  g_xd[N_NODES];          // x[n] * dinv[n]
__device__ float  g_t[N_NODES];           // unscaled layer-1 agg (seeded with xd)
__device__ float2 g_hhd[N_NODES];         // hh[n] * dinv[n]  (gather source, read-only in pass C)
__device__ float2 g_u[N_NODES];           // unscaled layer-2 agg (seeded with hhd)
__device__ double g_sum, g_sumsq;
__device__ float  g_S[HIDDEN], g_T[HIDDEN];
__device__ float  g_pool[N_GRAPHS * 2];
__device__ float  g_cnt[N_GRAPHS];

// K1: zero deg accumulator + small accumulators
__global__ void k_init() {
    int n = blockIdx.x * blockDim.x + threadIdx.x;
    if (n < N_NODES) g_dinv[n] = 0.0f;
    if (n < N_GRAPHS * 2) g_pool[n] = 0.0f;
    if (n < N_GRAPHS)     g_cnt[n] = 0.0f;
    if (n == 0) { g_sum = 0.0; g_sumsq = 0.0; }
}

// K2: deg[d] += w  (x4 vectorized)
__global__ void k_deg(const int4* __restrict__ dst4, const float4* __restrict__ ew4) {
    int i = blockIdx.x * blockDim.x + threadIdx.x;
    if (i >= N_EDGES / 4) return;
    int4   d = __ldg(&dst4[i]);
    float4 w = __ldg(&ew4[i]);
    atomicAdd(&g_dinv[d.x], w.x);
    atomicAdd(&g_dinv[d.y], w.y);
    atomicAdd(&g_dinv[d.z], w.z);
    atomicAdd(&g_dinv[d.w], w.w);
}

// K3: dinv = rsqrt(deg + 1 self-loop); xd = x*dinv; seed t with xd (self-loop term)
__global__ void k_dinv(const float* __restrict__ x) {
    int n = blockIdx.x * blockDim.x + threadIdx.x;
    if (n >= N_NODES) return;
    float di = rsqrtf(g_dinv[n] + 1.0f);
    float xd = __ldg(&x[n]) * di;
    g_dinv[n] = di;
    g_xd[n]   = xd;
    g_t[n]    = xd;     // self-loop: t[d] gets x[d]*dinv[d]; final a = dinv[d]*t[d]
}

// K4: edge pass B — t[d] += xd[s]*w   (x4 vectorized, 1 gather + 1 atomic per edge)
__global__ void k_agg1(const int4* __restrict__ src4, const int4* __restrict__ dst4,
                       const float4* __restrict__ ew4) {
    int i = blockIdx.x * blockDim.x + threadIdx.x;
    if (i >= N_EDGES / 4) return;
    int4   s = __ldg(&src4[i]);
    int4   d = __ldg(&dst4[i]);
    float4 w = __ldg(&ew4[i]);
    atomicAdd(&g_t[d.x], g_xd[s.x] * w.x);
    atomicAdd(&g_t[d.y], g_xd[s.y] * w.y);
    atomicAdd(&g_t[d.z], g_xd[s.z] * w.z);
    atomicAdd(&g_t[d.w], g_xd[s.w] * w.w);
}

// K5: mean/var of a_n = dinv[n]*t[n]
__global__ void k_reduce() {
    __shared__ float ss[256], sq[256];
    int tid = threadIdx.x;
    float a = 0.f, b = 0.f;
    for (int n = blockIdx.x * blockDim.x + tid; n < N_NODES; n += gridDim.x * blockDim.x) {
        float v = g_dinv[n] * g_t[n];
        a += v; b += v * v;
    }
    ss[tid] = a; sq[tid] = b;
    __syncthreads();
    for (int st = 128; st > 0; st >>= 1) {
        if (tid < st) { ss[tid] += ss[tid + st]; sq[tid] += sq[tid + st]; }
        __syncthreads();
    }
    if (tid == 0) {
        atomicAdd(&g_sum,   (double)ss[0]);
        atomicAdd(&g_sumsq, (double)sq[0]);
    }
}

// K6: fold bn + gamma/beta into per-column affine S_j, T_j
__global__ void k_bnconst(const float* __restrict__ W1, const float* __restrict__ b1,
                          const float* __restrict__ gamma, const float* __restrict__ beta) {
    int j = threadIdx.x;
    if (j >= HIDDEN) return;
    float m   = (float)(g_sum / (double)N_NODES);
    float var = (float)(g_sumsq / (double)N_NODES) - m * m;
    float w   = __ldg(&W1[j]);
    float inv = rsqrtf(var * w * w + 1e-5f);
    float sj  = w * inv * __ldg(&gamma[j]);
    g_S[j] = sj;
    g_T[j] = __ldg(&beta[j]) - m * sj;
}

// K7: hh[n] = relu(a_n*S+T) @ W2 ; store hhd = hh*dinv and seed u = hhd (self-loop)
__global__ void k_hh(const float* __restrict__ W2) {
    __shared__ float sS[HIDDEN], sT[HIDDEN], sW0[HIDDEN], sW1[HIDDEN];
    int tid = threadIdx.x;
    if (tid < HIDDEN) {
        sS[tid]  = g_S[tid];
        sT[tid]  = g_T[tid];
        sW0[tid] = __ldg(&W2[tid * EMB + 0]);
        sW1[tid] = __ldg(&W2[tid * EMB + 1]);
    }
    __syncthreads();
    int n = blockIdx.x * blockDim.x + tid;
    if (n >= N_NODES) return;
    float di = g_dinv[n];
    float a  = di * g_t[n];
    float acc0 = 0.f, acc1 = 0.f;
#pragma unroll
    for (int j = 0; j < HIDDEN; j++) {
        float h = fmaxf(fmaf(a, sS[j], sT[j]), 0.0f);
        acc0 = fmaf(h, sW0[j], acc0);
        acc1 = fmaf(h, sW1[j], acc1);
    }
    float2 hhd = make_float2(acc0 * di, acc1 * di);
    g_hhd[n] = hhd;     // gather source (read-only during pass C)
    g_u[n]   = hhd;     // self-loop seed: out2[d] = dinv[d]*(Σ hhd[s]*w + hhd[d])
}

// K8: edge pass C — u[d] += hhd[s]*w   (x4 loads, float2 vector atomic)
__global__ void k_agg2(const int4* __restrict__ src4, const int4* __restrict__ dst4,
                       const float4* __restrict__ ew4) {
    int i = blockIdx.x * blockDim.x + threadIdx.x;
    if (i >= N_EDGES / 4) return;
    int4   s = __ldg(&src4[i]);
    int4   d = __ldg(&dst4[i]);
    float4 w = __ldg(&ew4[i]);
    float2 h0 = g_hhd[s.x];
    float2 h1 = g_hhd[s.y];
    float2 h2 = g_hhd[s.z];
    float2 h3 = g_hhd[s.w];
    atomicAdd(&g_u[d.x], make_float2(h0.x * w.x, h0.y * w.x));
    atomicAdd(&g_u[d.y], make_float2(h1.x * w.y, h1.y * w.y));
    atomicAdd(&g_u[d.z], make_float2(h2.x * w.z, h2.y * w.z));
    atomicAdd(&g_u[d.w], make_float2(h3.x * w.w, h3.y * w.w));
}

// K9: pool out2[n] = dinv[n]*u[n] — smem pre-aggregation per block
__global__ void k_pool(const int* __restrict__ batch) {
    __shared__ float p0[N_GRAPHS], p1[N_GRAPHS], pc[N_GRAPHS];
    int tid = threadIdx.x;
    if (tid < N_GRAPHS) { p0[tid] = 0.f; p1[tid] = 0.f; pc[tid] = 0.f; }
    __syncthreads();
    int n = blockIdx.x * blockDim.x + tid;
    if (n < N_NODES) {
        int g = __ldg(&batch[n]);
        float di = g_dinv[n];
        float2 v = g_u[n];
        atomicAdd(&p0[g], v.x * di);
        atomicAdd(&p1[g], v.y * di);
        atomicAdd(&pc[g], 1.0f);
    }
    __syncthreads();
    if (tid < N_GRAPHS) {
        if (pc[tid] != 0.f) {
            atomicAdd(&g_pool[tid * 2 + 0], p0[tid]);
            atomicAdd(&g_pool[tid * 2 + 1], p1[tid]);
            atomicAdd(&g_cnt[tid], pc[tid]);
        }
    }
}

// K10: divide + b2
__global__ void k_final(const float* __restrict__ b2, float* __restrict__ out) {
    int g = threadIdx.x;
    if (g >= N_GRAPHS) return;
    float c = fmaxf(g_cnt[g], 1.0f);
    out[g * 2 + 0] = g_pool[g * 2 + 0] / c + __ldg(&b2[0]);
    out[g * 2 + 1] = g_pool[g * 2 + 1] / c + __ldg(&b2[1]);
}

extern "C" void kernel_launch(void* const* d_in, const int* in_sizes, int n_in,
                              void* d_out, int out_size) {
    const float* x     = (const float*)d_in[0];
    const int*   ei    = (const int*)  d_in[1];   // [2, E]
    const float* ew    = (const float*)d_in[2];
    const int*   batch = (const int*)  d_in[3];
    const float* W1    = (const float*)d_in[4];
    const float* b1    = (const float*)d_in[5];
    const float* gamma = (const float*)d_in[6];
    const float* beta  = (const float*)d_in[7];
    const float* W2    = (const float*)d_in[8];
    const float* b2    = (const float*)d_in[9];
    float* out = (float*)d_out;

    const int4*   src4 = (const int4*)  ei;
    const int4*   dst4 = (const int4*) (ei + N_EDGES);
    const float4* ew4  = (const float4*) ew;

    const int BT = 256;
    const int GN  = (N_NODES + BT - 1) / BT;
    const int GE4 = (N_EDGES / 4 + BT - 1) / BT;

    k_init   <<<GN, BT>>>();
    k_deg    <<<GE4, BT>>>(dst4, ew4);
    k_dinv   <<<GN, BT>>>(x);
    k_agg1   <<<GE4, BT>>>(src4, dst4, ew4);
    k_reduce <<<148, 256>>>();
    k_bnconst<<<1, 64>>>(W1, b1, gamma, beta);
    k_hh     <<<GN, BT>>>(W2);
    k_agg2   <<<GE4, BT>>>(src4, dst4, ew4);
    k_pool   <<<GN, BT>>>(batch);
    k_final  <<<1, 64>>>(b2, out);
}

// round 3
// speedup vs baseline: 1.4818x; 1.2402x over previous
#include <cuda_runtime.h>

#define N_NODES  100000
#define N_EDGES  1600000
#define HIDDEN   64
#define EMB      2
#define N_GRAPHS 64
#define NQ       (N_EDGES / 4)       // 400000 int4-quads

// -------- scratch (device globals) --------
__device__ float    g_dinv[N_NODES];     // deg -> rsqrt(deg+1)
__device__ float    g_xd[N_NODES];       // x[n] * dinv[n]
__device__ float    g_t[N_NODES];        // unscaled layer-1 agg (seeded with xd)
__device__ float2   g_hhd[N_NODES];      // hh[n] * dinv[n]
__device__ float2   g_u[N_NODES];        // unscaled layer-2 agg (seeded with hhd)
__device__ double   g_sum, g_sumsq;
__device__ float    g_pool[N_GRAPHS * 2];
__device__ float    g_cnt[N_GRAPHS];
__device__ unsigned g_done;

// K1: zero accumulators
__global__ void k_init() {
    int n = blockIdx.x * blockDim.x + threadIdx.x;
    if (n < N_NODES) g_dinv[n] = 0.0f;
    if (n < N_GRAPHS * 2) g_pool[n] = 0.0f;
    if (n < N_GRAPHS)     g_cnt[n] = 0.0f;
    if (n == 0) { g_sum = 0.0; g_sumsq = 0.0; g_done = 0u; }
}

// K2: deg[d] += w   (8 edges per thread)
__global__ void k_deg(const int4* __restrict__ dst4, const float4* __restrict__ ew4) {
    int i = (blockIdx.x * blockDim.x + threadIdx.x) * 2;
    if (i >= NQ) return;
    int4   d0 = __ldg(&dst4[i]),  d1 = __ldg(&dst4[i + 1]);
    float4 w0 = __ldg(&ew4[i]),   w1 = __ldg(&ew4[i + 1]);
    atomicAdd(&g_dinv[d0.x], w0.x); atomicAdd(&g_dinv[d0.y], w0.y);
    atomicAdd(&g_dinv[d0.z], w0.z); atomicAdd(&g_dinv[d0.w], w0.w);
    atomicAdd(&g_dinv[d1.x], w1.x); atomicAdd(&g_dinv[d1.y], w1.y);
    atomicAdd(&g_dinv[d1.z], w1.z); atomicAdd(&g_dinv[d1.w], w1.w);
}

// K3: dinv = rsqrt(deg+1); xd = x*dinv; seed t (self-loop)
__global__ void k_dinv(const float* __restrict__ x) {
    int n = blockIdx.x * blockDim.x + threadIdx.x;
    if (n >= N_NODES) return;
    float di = rsqrtf(g_dinv[n] + 1.0f);
    float xd = __ldg(&x[n]) * di;
    g_dinv[n] = di;
    g_xd[n]   = xd;
    g_t[n]    = xd;
}

// K4: t[d] += xd[s]*w   (8 edges per thread: 8 gathers in flight)
__global__ void k_agg1(const int4* __restrict__ src4, const int4* __restrict__ dst4,
                       const float4* __restrict__ ew4) {
    int i = (blockIdx.x * blockDim.x + threadIdx.x) * 2;
    if (i >= NQ) return;
    int4   s0 = __ldg(&src4[i]), s1 = __ldg(&src4[i + 1]);
    int4   d0 = __ldg(&dst4[i]), d1 = __ldg(&dst4[i + 1]);
    float4 w0 = __ldg(&ew4[i]),  w1 = __ldg(&ew4[i + 1]);
    float x0 = g_xd[s0.x], x1 = g_xd[s0.y], x2 = g_xd[s0.z], x3 = g_xd[s0.w];
    float x4 = g_xd[s1.x], x5 = g_xd[s1.y], x6 = g_xd[s1.z], x7 = g_xd[s1.w];
    atomicAdd(&g_t[d0.x], x0 * w0.x); atomicAdd(&g_t[d0.y], x1 * w0.y);
    atomicAdd(&g_t[d0.z], x2 * w0.z); atomicAdd(&g_t[d0.w], x3 * w0.w);
    atomicAdd(&g_t[d1.x], x4 * w1.x); atomicAdd(&g_t[d1.y], x5 * w1.y);
    atomicAdd(&g_t[d1.z], x6 * w1.z); atomicAdd(&g_t[d1.w], x7 * w1.w);
}

// K5: mean/var of a_n = dinv[n]*t[n]
__global__ void k_reduce() {
    __shared__ float ss[8], sq[8];
    int tid = threadIdx.x, lane = tid & 31, wrp = tid >> 5;
    float a = 0.f, b = 0.f;
    for (int n = blockIdx.x * blockDim.x + tid; n < N_NODES; n += gridDim.x * blockDim.x) {
        float v = g_dinv[n] * g_t[n];
        a += v; b += v * v;
    }
#pragma unroll
    for (int o = 16; o; o >>= 1) {
        a += __shfl_down_sync(0xffffffffu, a, o);
        b += __shfl_down_sync(0xffffffffu, b, o);
    }
    if (lane == 0) { ss[wrp] = a; sq[wrp] = b; }
    __syncthreads();
    if (wrp == 0) {
        a = (lane < 8) ? ss[lane] : 0.f;
        b = (lane < 8) ? sq[lane] : 0.f;
#pragma unroll
        for (int o = 4; o; o >>= 1) {
            a += __shfl_down_sync(0xffffffffu, a, o);
            b += __shfl_down_sync(0xffffffffu, b, o);
        }
        if (lane == 0) {
            atomicAdd(&g_sum,   (double)a);
            atomicAdd(&g_sumsq, (double)b);
        }
    }
}

// K6: (bnconst fused) hh[n] = relu(a_n*S+T) @ W2 ; hhd = hh*dinv ; seed u
__global__ void k_hh(const float* __restrict__ W1, const float* __restrict__ gamma,
                     const float* __restrict__ beta, const float* __restrict__ W2) {
    __shared__ float sS[HIDDEN], sT[HIDDEN], sW0[HIDDEN], sW1[HIDDEN];
    int tid = threadIdx.x;
    if (tid < HIDDEN) {
        float m   = (float)(g_sum / (double)N_NODES);
        float var = (float)(g_sumsq / (double)N_NODES) - m * m;
        float w   = __ldg(&W1[tid]);
        float inv = rsqrtf(var * w * w + 1e-5f);
        float sj  = w * inv * __ldg(&gamma[tid]);
        sS[tid] = sj;
        sT[tid] = __ldg(&beta[tid]) - m * sj;
        sW0[tid] = __ldg(&W2[tid * EMB + 0]);
        sW1[tid] = __ldg(&W2[tid * EMB + 1]);
    }
    __syncthreads();
    int n = blockIdx.x * blockDim.x + tid;
    if (n >= N_NODES) return;
    float di = g_dinv[n];
    float a  = di * g_t[n];
    float acc0 = 0.f, acc1 = 0.f;
#pragma unroll
    for (int j = 0; j < HIDDEN; j++) {
        float h = fmaxf(fmaf(a, sS[j], sT[j]), 0.0f);
        acc0 = fmaf(h, sW0[j], acc0);
        acc1 = fmaf(h, sW1[j], acc1);
    }
    float2 hhd = make_float2(acc0 * di, acc1 * di);
    g_hhd[n] = hhd;
    g_u[n]   = hhd;
}

// K7: u[d] += hhd[s]*w   (8 edges per thread, float2 vector atomics)
__global__ void k_agg2(const int4* __restrict__ src4, const int4* __restrict__ dst4,
                       const float4* __restrict__ ew4) {
    int i = (blockIdx.x * blockDim.x + threadIdx.x) * 2;
    if (i >= NQ) return;
    int4   s0 = __ldg(&src4[i]), s1 = __ldg(&src4[i + 1]);
    int4   d0 = __ldg(&dst4[i]), d1 = __ldg(&dst4[i + 1]);
    float4 w0 = __ldg(&ew4[i]),  w1 = __ldg(&ew4[i + 1]);
    float2 h0 = g_hhd[s0.x], h1 = g_hhd[s0.y], h2 = g_hhd[s0.z], h3 = g_hhd[s0.w];
    float2 h4 = g_hhd[s1.x], h5 = g_hhd[s1.y], h6 = g_hhd[s1.z], h7 = g_hhd[s1.w];
    atomicAdd(&g_u[d0.x], make_float2(h0.x * w0.x, h0.y * w0.x));
    atomicAdd(&g_u[d0.y], make_float2(h1.x * w0.y, h1.y * w0.y));
    atomicAdd(&g_u[d0.z], make_float2(h2.x * w0.z, h2.y * w0.z));
    atomicAdd(&g_u[d0.w], make_float2(h3.x * w0.w, h3.y * w0.w));
    atomicAdd(&g_u[d1.x], make_float2(h4.x * w1.x, h4.y * w1.x));
    atomicAdd(&g_u[d1.y], make_float2(h5.x * w1.y, h5.y * w1.y));
    atomicAdd(&g_u[d1.z], make_float2(h6.x * w1.z, h6.y * w1.z));
    atomicAdd(&g_u[d1.w], make_float2(h7.x * w1.w, h7.y * w1.w));
}

// K8: warp-aggregated pool + fused finalize (last block writes output)
__global__ void k_pool(const int* __restrict__ batch, const float* __restrict__ b2,
                       float* __restrict__ out) {
    int tid = threadIdx.x;
    int n = blockIdx.x * blockDim.x + tid;
    bool valid = n < N_NODES;
    int g = 0; float vx = 0.f, vy = 0.f, c = 0.f;
    if (valid) {
        g = __ldg(&batch[n]);
        float di = g_dinv[n];
        float2 u = g_u[n];
        vx = u.x * di; vy = u.y * di; c = 1.f;
    }
    // batch is sorted: warps are almost always graph-uniform.
    // lane 0 is always valid if any lane is (n increases with lane).
    int g0 = __shfl_sync(0xffffffffu, g, 0);
    bool uni = __all_sync(0xffffffffu, (g == g0) || !valid);
    if (uni) {
#pragma unroll
        for (int o = 16; o; o >>= 1) {
            vx += __shfl_down_sync(0xffffffffu, vx, o);
            vy += __shfl_down_sync(0xffffffffu, vy, o);
            c  += __shfl_down_sync(0xffffffffu, c,  o);
        }
        if ((tid & 31) == 0 && c > 0.f) {
            atomicAdd(&g_pool[g0 * 2 + 0], vx);
            atomicAdd(&g_pool[g0 * 2 + 1], vy);
            atomicAdd(&g_cnt[g0], c);
        }
    } else if (valid) {
        atomicAdd(&g_pool[g * 2 + 0], vx);
        atomicAdd(&g_pool[g * 2 + 1], vy);
        atomicAdd(&g_cnt[g], 1.0f);
    }
    // last-block-done finalize
    __shared__ bool last;
    __threadfence();
    __syncthreads();
    if (tid == 0) last = (atomicAdd(&g_done, 1u) == gridDim.x - 1);
    __syncthreads();
    if (last && tid < N_GRAPHS) {
        float cc = fmaxf(g_cnt[tid], 1.0f);
        out[tid * 2 + 0] = g_pool[tid * 2 + 0] / cc + __ldg(&b2[0]);
        out[tid * 2 + 1] = g_pool[tid * 2 + 1] / cc + __ldg(&b2[1]);
    }
}

extern "C" void kernel_launch(void* const* d_in, const int* in_sizes, int n_in,
                              void* d_out, int out_size) {
    const float* x     = (const float*)d_in[0];
    const int*   ei    = (const int*)  d_in[1];   // [2, E]
    const float* ew    = (const float*)d_in[2];
    const int*   batch = (const int*)  d_in[3];
    const float* W1    = (const float*)d_in[4];
    const float* gamma = (const float*)d_in[6];
    const float* beta  = (const float*)d_in[7];
    const float* W2    = (const float*)d_in[8];
    const float* b2    = (const float*)d_in[9];
    float* out = (float*)d_out;

    const int4*   src4 = (const int4*)  ei;
    const int4*   dst4 = (const int4*) (ei + N_EDGES);
    const float4* ew4  = (const float4*) ew;

    const int BT  = 256;
    const int GN  = (N_NODES + BT - 1) / BT;
    const int GE8 = (NQ / 2 + BT - 1) / BT;    // 8 edges per thread

    k_init  <<<GN, BT>>>();
    k_deg   <<<GE8, BT>>>(dst4, ew4);
    k_dinv  <<<GN, BT>>>(x);
    k_agg1  <<<GE8, BT>>>(src4, dst4, ew4);
    k_reduce<<<148, 256>>>();
    k_hh    <<<GN, BT>>>(W1, gamma, beta, W2);
    k_agg2  <<<GE8, BT>>>(src4, dst4, ew4);
    k_pool  <<<GN, BT>>>(batch, b2, out);
}